// round 2
// baseline (speedup 1.0000x reference)
#include <cuda_runtime.h>
#include <cooperative_groups.h>
#include <math.h>
#include <stdint.h>

namespace cg = cooperative_groups;

#define B_    8
#define T_    512
#define DIM_  512
#define R_    2048
#define BT_   4096
#define FFH_MAX 1376

// ---------------- device scratch (allocation-free rule) ----------------
__device__ float g_qWi [R_*DIM_];
__device__ float g_qW1 [2*DIM_*R_];
__device__ float g_qW2 [DIM_*2*DIM_];
__device__ float g_qWqkv[3*DIM_*DIM_];
__device__ float g_qWo [DIM_*DIM_];
__device__ float g_qWf1[FFH_MAX*DIM_];
__device__ float g_qWf2[DIM_*FFH_MAX];
__device__ float g_qWf3[FFH_MAX*DIM_];
__device__ unsigned g_pm[64*R_];
__device__ unsigned g_nm[64*R_];
__device__ float g_xp  [(size_t)BT_*R_];
__device__ float g_acts[(size_t)BT_*R_];
__device__ float g_hn  [(size_t)BT_*R_];
__device__ float g_h   [(size_t)BT_*2*DIM_];
__device__ float g_y   [(size_t)BT_*DIM_];
__device__ float g_xa  [(size_t)BT_*DIM_];
__device__ float g_qkv [(size_t)BT_*3*DIM_];
__device__ float g_sc  [(size_t)64*T_*T_];
__device__ float g_o   [(size_t)BT_*DIM_];
__device__ float g_xres[(size_t)BT_*DIM_];
__device__ float g_xf  [(size_t)BT_*DIM_];
__device__ float g_g   [(size_t)BT_*FFH_MAX];
__device__ float g_gu  [(size_t)BT_*FFH_MAX];
__device__ float g_red [256];
__device__ float g_thr [1];

// ---------------- ternary quantization ---------------------------------
__global__ void absmean_partial(const float* __restrict__ w, int n, float* __restrict__ partial) {
    __shared__ float sm[256];
    float acc = 0.f;
    int stride = gridDim.x * 256;
    for (int i = blockIdx.x * 256 + threadIdx.x; i < n; i += stride) acc += fabsf(w[i]);
    sm[threadIdx.x] = acc; __syncthreads();
    for (int s = 128; s > 0; s >>= 1) {
        if (threadIdx.x < s) sm[threadIdx.x] += sm[threadIdx.x + s];
        __syncthreads();
    }
    if (threadIdx.x == 0) partial[blockIdx.x] = sm[0];
}

__global__ void absmean_final(const float* __restrict__ partial, int n, float* __restrict__ thr_out) {
    __shared__ float sm[256];
    sm[threadIdx.x] = partial[threadIdx.x]; __syncthreads();
    for (int s = 128; s > 0; s >>= 1) {
        if (threadIdx.x < s) sm[threadIdx.x] += sm[threadIdx.x + s];
        __syncthreads();
    }
    if (threadIdx.x == 0) thr_out[0] = __fmul_rn(__fdiv_rn(sm[0], (float)n), 0.7f);
}

// effective quantized weight = w + (q - w) with fp32 rounding (matches STE forward bit-exact)
__global__ void quantize_k(const float* __restrict__ w, const float* __restrict__ thr,
                           float* __restrict__ out, int n) {
    int i = blockIdx.x * 256 + threadIdx.x;
    if (i < n) {
        float v = w[i], t = thr[0];
        float q = (fabsf(v) > t) ? (v > 0.f ? 1.f : -1.f) : 0.f;
        out[i] = __fadd_rn(v, __fsub_rn(q, v));
    }
}

// Wr -> pos/neg bitmasks; layout pm[word*R + r] for coalesced scan loads
__global__ void build_masks(const float* __restrict__ Wr, const float* __restrict__ thr,
                            unsigned* __restrict__ pm, unsigned* __restrict__ nm) {
    int r = blockIdx.x;
    int w = threadIdx.x;           // 64 words
    float t = thr[0];
    const float* row = Wr + (size_t)r * R_ + w * 32;
    unsigned p = 0u, ng = 0u;
    #pragma unroll
    for (int i = 0; i < 32; i++) {
        float v = row[i];
        if (fabsf(v) > t) { if (v > 0.f) p |= (1u << i); else ng |= (1u << i); }
    }
    pm[w * R_ + r] = p;
    nm[w * R_ + r] = ng;
}

// ---------------- generic fp32 SGEMM ------------------------------------
// C = epi(alpha*A.op(B) + bias). TB: B is W[N,K] (C=A.Wt) else B[K,N].
// EPI: 0 none, 1 gelu(exact), 2 silu, 3 v*extra, 4 extra+v
template<int EPI, bool TB>
__global__ void __launch_bounds__(256)
gemm_k(const float* __restrict__ A, const float* __restrict__ Bm,
       const float* __restrict__ bias, const float* __restrict__ extra,
       float* __restrict__ C,
       int M, int N, int K, int lda, int ldb, int ldc, int lde,
       long aZ1, long aZ2, long bZ1, long bZ2, long cZ1, long cZ2,
       int zInner, float alpha)
{
    int z = blockIdx.z;
    int zo = z / zInner, zi = z - zo * zInner;
    A  += zo * aZ1 + zi * aZ2;
    Bm += zo * bZ1 + zi * bZ2;
    C  += zo * cZ1 + zi * cZ2;

    __shared__ float As[8][132];
    __shared__ float Bs[8][132];
    int tid = threadIdx.x;
    int row0 = blockIdx.y * 128, col0 = blockIdx.x * 128;
    int ty = tid >> 4, tx = tid & 15;

    float acc[8][8];
    #pragma unroll
    for (int i = 0; i < 8; i++)
        #pragma unroll
        for (int j = 0; j < 8; j++) acc[i][j] = 0.f;

    for (int kt = 0; kt < K; kt += 8) {
        #pragma unroll
        for (int l = 0; l < 4; l++) {
            int idx = tid + l * 256;
            int m = idx >> 3, k = idx & 7;
            int gm = row0 + m, gk = kt + k;
            As[k][m] = (gm < M && gk < K) ? A[(size_t)gm * lda + gk] : 0.f;
        }
        if (TB) {
            #pragma unroll
            for (int l = 0; l < 4; l++) {
                int idx = tid + l * 256;
                int n = idx >> 3, k = idx & 7;
                int gn = col0 + n, gk = kt + k;
                Bs[k][n] = (gn < N && gk < K) ? Bm[(size_t)gn * ldb + gk] : 0.f;
            }
        } else {
            #pragma unroll
            for (int l = 0; l < 4; l++) {
                int idx = tid + l * 256;
                int k = idx >> 7, n = idx & 127;
                int gn = col0 + n, gk = kt + k;
                Bs[k][n] = (gn < N && gk < K) ? Bm[(size_t)gk * ldb + gn] : 0.f;
            }
        }
        __syncthreads();
        #pragma unroll
        for (int k = 0; k < 8; k++) {
            float av[8], bv[8];
            #pragma unroll
            for (int i = 0; i < 8; i++) av[i] = As[k][ty * 8 + i];
            #pragma unroll
            for (int j = 0; j < 8; j++) bv[j] = Bs[k][tx * 8 + j];
            #pragma unroll
            for (int i = 0; i < 8; i++)
                #pragma unroll
                for (int j = 0; j < 8; j++) acc[i][j] += av[i] * bv[j];
        }
        __syncthreads();
    }

    #pragma unroll
    for (int i = 0; i < 8; i++) {
        int gm = row0 + ty * 8 + i;
        if (gm >= M) continue;
        #pragma unroll
        for (int j = 0; j < 8; j++) {
            int gn = col0 + tx * 8 + j;
            if (gn >= N) continue;
            float v = acc[i][j] * alpha;
            if (bias) v = __fadd_rn(v, bias[gn]);
            if (EPI == 1) {
                v = 0.5f * v * (1.0f + erff(v * 0.70710678118654752f));
            } else if (EPI == 2) {
                v = v / (1.0f + expf(-v));
            } else if (EPI == 3) {
                v = v * extra[(size_t)gm * lde + gn];
            } else if (EPI == 4) {
                v = __fadd_rn(extra[(size_t)gm * lde + gn], v);
            }
            C[(size_t)gm * ldc + gn] = v;
        }
    }
}

// ---------------- LIF scan: one 8-CTA cluster per batch -----------------
__global__ void __cluster_dims__(8, 1, 1) __launch_bounds__(256, 1)
scan_kernel(const float* __restrict__ xp,
            const float* __restrict__ beta, const float* __restrict__ sfa_inc,
            const float* __restrict__ sfa_decay,
            const unsigned* __restrict__ pmask, const unsigned* __restrict__ nmask,
            float* __restrict__ acts)
{
    cg::cluster_group cl = cg::this_cluster();
    int crank = (int)cl.block_rank();
    int b = blockIdx.x >> 3;
    int tid = threadIdx.x;
    int r = crank * 256 + tid;
    int lane = tid & 31;
    int gw = r >> 5;

    __shared__ unsigned s_spk[2][64];
    if (tid < 64) { s_spk[0][tid] = 0u; s_spk[1][tid] = 0u; }

    unsigned pm[64], nm[64];
    #pragma unroll
    for (int w = 0; w < 64; w++) { pm[w] = pmask[w * R_ + r]; nm[w] = nmask[w * R_ + r]; }

    float beta_r = beta[r], dec = sfa_decay[r], inc = sfa_inc[r];
    float mem = 0.f, ath = 0.f;
    const float* __restrict__ xrow = xp + (size_t)b * T_ * R_ + r;
    float* __restrict__ arow = acts + (size_t)b * T_ * R_ + r;

    cl.sync();

    for (int t = 0; t < T_; t++) {
        int pb = t & 1, wb = pb ^ 1;
        int acc = 0;
        #pragma unroll
        for (int w = 0; w < 64; w++) {
            unsigned s = s_spk[pb][w];
            acc += __popc(pm[w] & s);
            acc -= __popc(nm[w] & s);
        }
        float cur = __fadd_rn(xrow[(size_t)t * R_], (float)acc);
        mem = __fadd_rn(__fmul_rn(beta_r, mem), cur);
        float th = __fadd_rn(1.0f, ath);
        bool sp = __fsub_rn(mem, th) > 0.0f;
        float spk = sp ? 1.0f : 0.0f;
        if (sp) mem = 0.0f;
        ath = __fadd_rn(__fmul_rn(dec, ath), __fmul_rn(inc, spk));
        arow[(size_t)t * R_] = spk;

        unsigned bal = __ballot_sync(0xffffffffu, sp);
        if (lane == 0) {
            #pragma unroll
            for (int dst = 0; dst < 8; dst++) {
                unsigned* rp = (unsigned*)cl.map_shared_rank(&s_spk[wb][gw], dst);
                *rp = bal;
            }
        }
        cl.sync();
    }
}

// ---------------- rmsnorm ------------------------------------------------
__global__ void rmsnorm_k(const float* __restrict__ x, const float* __restrict__ w,
                          float* __restrict__ out, int N) {
    int row = blockIdx.x;
    const float* xr = x + (size_t)row * N;
    float* orow = out + (size_t)row * N;
    __shared__ float sm[256];
    __shared__ float s_scale;
    float acc = 0.f;
    for (int i = threadIdx.x; i < N; i += 256) { float v = xr[i]; acc += v * v; }
    sm[threadIdx.x] = acc; __syncthreads();
    for (int s = 128; s > 0; s >>= 1) {
        if (threadIdx.x < s) sm[threadIdx.x] += sm[threadIdx.x + s];
        __syncthreads();
    }
    if (threadIdx.x == 0)
        s_scale = rsqrtf(__fadd_rn(__fdiv_rn(sm[0], (float)N), 1e-6f));
    __syncthreads();
    float sc = s_scale;
    for (int i = threadIdx.x; i < N; i += 256)
        orow[i] = __fmul_rn(__fmul_rn(xr[i], sc), w[i]);
}

// ---------------- softmax over rows of 512 -------------------------------
__global__ void softmax_k(float* __restrict__ s) {
    int row = blockIdx.x;
    float* p = s + (size_t)row * 512;
    __shared__ float sm[128];
    int tid = threadIdx.x;
    float m = -3.402823466e38f;
    #pragma unroll
    for (int l = 0; l < 4; l++) m = fmaxf(m, p[tid + l * 128]);
    sm[tid] = m; __syncthreads();
    for (int st = 64; st > 0; st >>= 1) {
        if (tid < st) sm[tid] = fmaxf(sm[tid], sm[tid + st]);
        __syncthreads();
    }
    float M = sm[0]; __syncthreads();
    float e[4]; float acc = 0.f;
    #pragma unroll
    for (int l = 0; l < 4; l++) { e[l] = expf(p[tid + l * 128] - M); acc += e[l]; }
    sm[tid] = acc; __syncthreads();
    for (int st = 64; st > 0; st >>= 1) {
        if (tid < st) sm[tid] += sm[tid + st];
        __syncthreads();
    }
    float sum = sm[0];
    #pragma unroll
    for (int l = 0; l < 4; l++) p[tid + l * 128] = __fdiv_rn(e[l], sum);
}

// ---------------- host ---------------------------------------------------
template<typename T> static T* devptr(const void* sym) {
    void* p = nullptr; cudaGetSymbolAddress(&p, sym); return (T*)p;
}

static void ternarize(const float* src, float* dst, int n, float* red, float* thr) {
    absmean_partial<<<256, 256>>>(src, n, red);
    absmean_final<<<1, 256>>>(red, n, thr);
    quantize_k<<<(n + 255) / 256, 256>>>(src, thr, dst, n);
}

template<int EPI, bool TB>
static void G(const float* A, const float* Bm, const float* bias, const float* extra, float* C,
              int M, int N, int K, int lda, int ldb, int ldc, int lde,
              long aZ1, long aZ2, long bZ1, long bZ2, long cZ1, long cZ2,
              int zInner, int Z, float alpha) {
    dim3 grid((N + 127) / 128, (M + 127) / 128, Z);
    gemm_k<EPI, TB><<<grid, 256>>>(A, Bm, bias, extra, C, M, N, K, lda, ldb, ldc, lde,
                                   aZ1, aZ2, bZ1, bZ2, cZ1, cZ2, zInner, alpha);
}

extern "C" void kernel_launch(void* const* d_in, const int* in_sizes, int n_in,
                              void* d_out, int out_size) {
    const float* x        = (const float*)d_in[0];
    const float* Wi       = (const float*)d_in[1];
    const float* bi       = (const float*)d_in[2];
    const float* Wr       = (const float*)d_in[3];
    const float* rn_w     = (const float*)d_in[4];
    const float* W1       = (const float*)d_in[5];
    const float* b1       = (const float*)d_in[6];
    const float* W2       = (const float*)d_in[7];
    const float* b2       = (const float*)d_in[8];
    const float* anorm_w  = (const float*)d_in[9];
    const float* Wqkv     = (const float*)d_in[10];
    const float* Wo       = (const float*)d_in[11];
    const float* fnorm_w  = (const float*)d_in[12];
    const float* Wf1      = (const float*)d_in[13];
    const float* Wf2      = (const float*)d_in[14];
    const float* Wf3      = (const float*)d_in[15];
    const float* beta     = (const float*)d_in[16];
    const float* sfa_inc  = (const float*)d_in[17];
    const float* sfa_dec  = (const float*)d_in[18];
    float* out = (float*)d_out;
    const int FFH = in_sizes[13] / DIM_;

    float* red   = devptr<float>(g_red);
    float* thr   = devptr<float>(g_thr);
    float* qWi   = devptr<float>(g_qWi);
    float* qW1   = devptr<float>(g_qW1);
    float* qW2   = devptr<float>(g_qW2);
    float* qWqkv = devptr<float>(g_qWqkv);
    float* qWo   = devptr<float>(g_qWo);
    float* qWf1  = devptr<float>(g_qWf1);
    float* qWf2  = devptr<float>(g_qWf2);
    float* qWf3  = devptr<float>(g_qWf3);
    unsigned* pm = devptr<unsigned>(g_pm);
    unsigned* nm = devptr<unsigned>(g_nm);
    float* xp    = devptr<float>(g_xp);
    float* acts  = devptr<float>(g_acts);
    float* hn    = devptr<float>(g_hn);
    float* h     = devptr<float>(g_h);
    float* y     = devptr<float>(g_y);
    float* xa    = devptr<float>(g_xa);
    float* qkv   = devptr<float>(g_qkv);
    float* sc    = devptr<float>(g_sc);
    float* o     = devptr<float>(g_o);
    float* xres  = devptr<float>(g_xres);
    float* xf    = devptr<float>(g_xf);
    float* gbuf  = devptr<float>(g_g);
    float* gu    = devptr<float>(g_gu);

    // quantize weights
    ternarize(Wi,   qWi,   R_ * DIM_,       red, thr);
    ternarize(W1,   qW1,   2 * DIM_ * R_,   red, thr);
    ternarize(W2,   qW2,   DIM_ * 2 * DIM_, red, thr);
    ternarize(Wqkv, qWqkv, 3 * DIM_ * DIM_, red, thr);
    ternarize(Wo,   qWo,   DIM_ * DIM_,     red, thr);
    ternarize(Wf1,  qWf1,  FFH * DIM_,      red, thr);
    ternarize(Wf2,  qWf2,  DIM_ * FFH,      red, thr);
    ternarize(Wf3,  qWf3,  FFH * DIM_,      red, thr);
    // Wr -> bitmasks
    absmean_partial<<<256, 256>>>(Wr, R_ * R_, red);
    absmean_final<<<1, 256>>>(red, R_ * R_, thr);
    build_masks<<<R_, 64>>>(Wr, thr, pm, nm);

    // xp = x @ qWi^T + bi   [4096,2048] K=512
    G<0, true>(x, qWi, bi, nullptr, xp, BT_, R_, DIM_, DIM_, DIM_, R_, 0,
               0, 0, 0, 0, 0, 0, 1, 1, 1.f);

    // LIF scan
    scan_kernel<<<64, 256>>>(xp, beta, sfa_inc, sfa_dec, pm, nm, acts);

    // readout MLP
    rmsnorm_k<<<BT_, 256>>>(acts, rn_w, hn, R_);
    G<1, true>(hn, qW1, b1, nullptr, h, BT_, 2 * DIM_, R_, R_, R_, 2 * DIM_, 0,
               0, 0, 0, 0, 0, 0, 1, 1, 1.f);
    G<0, true>(h, qW2, b2, nullptr, y, BT_, DIM_, 2 * DIM_, 2 * DIM_, 2 * DIM_, DIM_, 0,
               0, 0, 0, 0, 0, 0, 1, 1, 1.f);

    // attention block
    rmsnorm_k<<<BT_, 256>>>(y, anorm_w, xa, DIM_);
    G<0, true>(xa, qWqkv, nullptr, nullptr, qkv, BT_, 3 * DIM_, DIM_, DIM_, DIM_, 3 * DIM_, 0,
               0, 0, 0, 0, 0, 0, 1, 1, 1.f);
    // scores[b,h] = q @ k^T * 1/8 : M=N=512 K=64, z = b*8+h
    G<0, true>(qkv, qkv + 512, nullptr, nullptr, sc, T_, T_, 64, 1536, 1536, T_, 0,
               (long)T_ * 1536, 64, (long)T_ * 1536, 64,
               (long)8 * T_ * T_, (long)T_ * T_, 8, 64, 0.125f);
    softmax_k<<<64 * T_, 128>>>(sc);
    // o[b,h] = attn @ v : M=512 N=64 K=512
    G<0, false>(sc, qkv + 1024, nullptr, nullptr, o, T_, 64, T_, T_, 1536, DIM_, 0,
                (long)8 * T_ * T_, (long)T_ * T_, (long)T_ * 1536, 64,
                (long)T_ * DIM_, 64, 8, 64, 1.f);
    // x_res = y + o @ qWo^T
    G<4, true>(o, qWo, nullptr, y, xres, BT_, DIM_, DIM_, DIM_, DIM_, DIM_, DIM_,
               0, 0, 0, 0, 0, 0, 1, 1, 1.f);

    // SwiGLU FFN
    rmsnorm_k<<<BT_, 256>>>(xres, fnorm_w, xf, DIM_);
    G<2, true>(xf, qWf1, nullptr, nullptr, gbuf, BT_, FFH, DIM_, DIM_, DIM_, FFH, 0,
               0, 0, 0, 0, 0, 0, 1, 1, 1.f);
    G<3, true>(xf, qWf3, nullptr, gbuf, gu, BT_, FFH, DIM_, DIM_, DIM_, FFH, FFH,
               0, 0, 0, 0, 0, 0, 1, 1, 1.f);
    G<4, true>(gu, qWf2, nullptr, xres, out, BT_, DIM_, FFH, FFH, FFH, DIM_, DIM_,
               0, 0, 0, 0, 0, 0, 1, 1, 1.f);
}